// round 4
// baseline (speedup 1.0000x reference)
#include <cuda_runtime.h>
#include <cstdint>
#include <float.h>

// Problem constants
constexpr int Bc = 2, Hc = 16, Sc = 2048, Dc = 64;
constexpr int BM = 128, BN = 64;
constexpr int LDP = 68;                   // smem row pad (floats), conflict-free frag reads
constexpr int TILE_F = 64 * LDP;          // floats per 64-row tensor tile
constexpr int SMEM_FLOATS = 4 * TILE_F;   // 2 stages x (K + V)
constexpr int SMEM_BYTES = SMEM_FLOATS * 4;  // 69,632 B
constexpr float SCL = 0.18033688011f;     // 0.125 * log2(e)

__device__ __forceinline__ uint32_t f2tf32(float f) {
    uint32_t u;
    asm("cvt.rna.tf32.f32 %0, %1;" : "=r"(u) : "f"(f));
    return u;
}

__device__ __forceinline__ float ex2(float x) {
    float y;
    asm("ex2.approx.ftz.f32 %0, %1;" : "=f"(y) : "f"(x));
    return y;
}

__device__ __forceinline__ void mma_tf32(float c[4], const uint32_t a[4],
                                         uint32_t b0, uint32_t b1) {
    asm volatile(
        "mma.sync.aligned.m16n8k8.row.col.f32.tf32.tf32.f32 "
        "{%0,%1,%2,%3}, {%4,%5,%6,%7}, {%8,%9}, {%0,%1,%2,%3};"
        : "+f"(c[0]), "+f"(c[1]), "+f"(c[2]), "+f"(c[3])
        : "r"(a[0]), "r"(a[1]), "r"(a[2]), "r"(a[3]), "r"(b0), "r"(b1));
}

__device__ __forceinline__ void cp_async16(uint32_t saddr, const void* gptr) {
    asm volatile("cp.async.cg.shared.global [%0], [%1], 16;" :: "r"(saddr), "l"(gptr));
}

// Flash-attention, tf32 mma.sync, double-buffered cp.async K/V pipeline.
// Grid (S/128, H, B), 8 warps; warp w owns q-rows [w*16, w*16+16). P stays in
// mma accumulators and is reused as the A operand of P@V (V k-rows permuted).
// Softmax runs in log2 domain (scale/bias pre-folded) using raw MUFU.EX2.
__global__ __launch_bounds__(256, 1)
void fa_tf32_pipe(const float* __restrict__ q, const float* __restrict__ k,
                  const float* __restrict__ v, const float* __restrict__ bias,
                  float* __restrict__ out)
{
    extern __shared__ float smem[];
    const uint32_t sbase = (uint32_t)__cvta_generic_to_shared(smem);

    // Reverse q-tile order: heaviest CTAs first.
    const int qt = (int)gridDim.x - 1 - (int)blockIdx.x;
    const int h = blockIdx.y;
    const int b = blockIdx.z;

    const int tid = threadIdx.x;
    const int wid = tid >> 5;
    const int lane = tid & 31;
    const int g = lane >> 2;
    const int t = lane & 3;
    const int i0w = wid * 16;

    const size_t bh = (size_t)b * Hc + h;
    const float* qb    = q    + (bh * Sc + (size_t)qt * BM) * Dc;
    const float* kb    = k    + bh * Sc * Dc;
    const float* vb    = v    + bh * Sc * Dc;
    const float* biasb = bias + (bh * Sc + (size_t)qt * BM) * Sc;
    float* outb        = out  + (bh * Sc + (size_t)qt * BM) * Dc;

    const int lrow = tid >> 4;         // loader row (16 rows per pass)
    const int lc4  = (tid & 15) << 2;  // loader col (float4 along d)

    // ---- Stage Q (raw fp32) into smem, extract per-warp tf32 A fragments ----
    #pragma unroll
    for (int p = 0; p < 8; p++) {
        const int r = lrow + p * 16;
        float4 qv = *reinterpret_cast<const float4*>(qb + (size_t)r * Dc + lc4);
        *reinterpret_cast<float4*>(&smem[r * LDP + lc4]) = qv;
    }
    __syncthreads();

    uint32_t qa[8][4];
    #pragma unroll
    for (int ks = 0; ks < 8; ks++) {
        qa[ks][0] = f2tf32(smem[(i0w + g)     * LDP + ks * 8 + t]);
        qa[ks][1] = f2tf32(smem[(i0w + g + 8) * LDP + ks * 8 + t]);
        qa[ks][2] = f2tf32(smem[(i0w + g)     * LDP + ks * 8 + t + 4]);
        qa[ks][3] = f2tf32(smem[(i0w + g + 8) * LDP + ks * 8 + t + 4]);
    }
    __syncthreads();  // Q staging region free (aliased by pipeline buffers)

    const int ntiles = 2 * qt + 2;

    // ---- Prologue: stream tile 0 into stage 0 ----
    {
        const int jb0 = 0;
        const uint32_t kdst = sbase + (0 * 2 * TILE_F) * 4;
        #pragma unroll
        for (int p = 0; p < 4; p++) {
            const int r = lrow + p * 16;
            cp_async16(kdst + (r * LDP + lc4) * 4,            kb + (size_t)(jb0 + r) * Dc + lc4);
            cp_async16(kdst + (TILE_F + r * LDP + lc4) * 4,   vb + (size_t)(jb0 + r) * Dc + lc4);
        }
        asm volatile("cp.async.commit_group;");
    }

    // Online-softmax state (log2 domain)
    float m[2] = {-FLT_MAX, -FLT_MAX};
    float l[2] = {0.f, 0.f};
    float o[8][4];
    #pragma unroll
    for (int nf = 0; nf < 8; nf++)
        #pragma unroll
        for (int e = 0; e < 4; e++) o[nf][e] = 0.f;

    for (int jt = 0; jt < ntiles; jt++) {
        const int jbase = jt * BN;
        const int cur = jt & 1;

        __syncthreads();  // stage (jt+1)&1 free of readers (compute jt-1 done)

        // ---- Issue cp.async for tile jt+1 into the alternate stage ----
        if (jt + 1 < ntiles) {
            const int jbn = jbase + BN;
            const uint32_t dst = sbase + (((jt + 1) & 1) * 2 * TILE_F) * 4;
            #pragma unroll
            for (int p = 0; p < 4; p++) {
                const int r = lrow + p * 16;
                cp_async16(dst + (r * LDP + lc4) * 4,          kb + (size_t)(jbn + r) * Dc + lc4);
                cp_async16(dst + (TILE_F + r * LDP + lc4) * 4, vb + (size_t)(jbn + r) * Dc + lc4);
            }
        }
        asm volatile("cp.async.commit_group;");

        const bool active = (qt * BM + i0w + 15) >= jbase;

        // ---- Bias prefetch (overlaps the cp.async wait + barrier) ----
        float c[8][4];
        if (active) {
            const float* bp0 = biasb + (size_t)(i0w + g) * Sc + jbase + 2 * t;
            const float* bp1 = bp0 + (size_t)8 * Sc;
            #pragma unroll
            for (int nf = 0; nf < 8; nf++) {
                float2 b0 = *reinterpret_cast<const float2*>(bp0 + nf * 8);
                float2 b1 = *reinterpret_cast<const float2*>(bp1 + nf * 8);
                c[nf][0] = b0.x * 8.f;
                c[nf][1] = b0.y * 8.f;
                c[nf][2] = b1.x * 8.f;
                c[nf][3] = b1.y * 8.f;
            }
        }

        asm volatile("cp.async.wait_group 1;");  // tile jt landed (this thread)
        __syncthreads();                          // ... and for all threads

        if (!active) continue;

        const float* sK = smem + cur * 2 * TILE_F;
        const float* sV = sK + TILE_F;

        // ---- GEMM1: C += Q @ K^T (K converted to tf32 at read) ----
        #pragma unroll
        for (int ks = 0; ks < 8; ks++) {
            #pragma unroll
            for (int nf = 0; nf < 8; nf++) {
                const uint32_t b0 = f2tf32(sK[(nf * 8 + g) * LDP + ks * 8 + t]);
                const uint32_t b1 = f2tf32(sK[(nf * 8 + g) * LDP + ks * 8 + t + 4]);
                mma_tf32(c[nf], qa[ks], b0, b1);
            }
        }

        // ---- Epilogue: fold scale*log2e (bias already inside), causal mask ----
        #pragma unroll
        for (int nf = 0; nf < 8; nf++)
            #pragma unroll
            for (int e = 0; e < 4; e++) c[nf][e] *= SCL;

        if (jt >= 2 * qt) {
            const int row0 = qt * BM + i0w + g;
            const int row1 = row0 + 8;
            #pragma unroll
            for (int nf = 0; nf < 8; nf++) {
                const int col = jbase + nf * 8 + 2 * t;
                if (col     > row0) c[nf][0] = -FLT_MAX;
                if (col + 1 > row0) c[nf][1] = -FLT_MAX;
                if (col     > row1) c[nf][2] = -FLT_MAX;
                if (col + 1 > row1) c[nf][3] = -FLT_MAX;
            }
        }

        // ---- Online softmax (log2 domain; row lanes = quad) ----
        #pragma unroll
        for (int r = 0; r < 2; r++) {
            float rmax = -FLT_MAX;
            #pragma unroll
            for (int nf = 0; nf < 8; nf++)
                rmax = fmaxf(rmax, fmaxf(c[nf][2 * r], c[nf][2 * r + 1]));
            rmax = fmaxf(rmax, __shfl_xor_sync(0xffffffffu, rmax, 1));
            rmax = fmaxf(rmax, __shfl_xor_sync(0xffffffffu, rmax, 2));
            const float mnew = fmaxf(m[r], rmax);
            const float alpha = ex2(m[r] - mnew);
            float rsum = 0.f;
            #pragma unroll
            for (int nf = 0; nf < 8; nf++) {
                const float p0 = ex2(c[nf][2 * r]     - mnew);
                const float p1 = ex2(c[nf][2 * r + 1] - mnew);
                c[nf][2 * r] = p0;
                c[nf][2 * r + 1] = p1;
                rsum += p0 + p1;
            }
            rsum += __shfl_xor_sync(0xffffffffu, rsum, 1);
            rsum += __shfl_xor_sync(0xffffffffu, rsum, 2);
            l[r] = l[r] * alpha + rsum;
            m[r] = mnew;
            #pragma unroll
            for (int nf = 0; nf < 8; nf++) {
                o[nf][2 * r]     *= alpha;
                o[nf][2 * r + 1] *= alpha;
            }
        }

        // ---- GEMM2: O += P @ V (P regs as A; V rows permuted to match) ----
        #pragma unroll
        for (int ks = 0; ks < 8; ks++) {
            uint32_t pa[4];
            pa[0] = f2tf32(c[ks][0]);
            pa[1] = f2tf32(c[ks][2]);
            pa[2] = f2tf32(c[ks][1]);
            pa[3] = f2tf32(c[ks][3]);
            #pragma unroll
            for (int nf = 0; nf < 8; nf++) {
                const uint32_t b0 = f2tf32(sV[(ks * 8 + 2 * t)     * LDP + nf * 8 + g]);
                const uint32_t b1 = f2tf32(sV[(ks * 8 + 2 * t + 1) * LDP + nf * 8 + g]);
                mma_tf32(o[nf], pa, b0, b1);
            }
        }
    }

    // ---- Finalize ----
    #pragma unroll
    for (int r = 0; r < 2; r++) {
        const float inv = 1.f / l[r];
        const int row = i0w + g + 8 * r;
        #pragma unroll
        for (int nf = 0; nf < 8; nf++) {
            float2 res = make_float2(o[nf][2 * r] * inv, o[nf][2 * r + 1] * inv);
            *reinterpret_cast<float2*>(outb + (size_t)row * Dc + nf * 8 + 2 * t) = res;
        }
    }
}

extern "C" void kernel_launch(void* const* d_in, const int* in_sizes, int n_in,
                              void* d_out, int out_size)
{
    (void)in_sizes; (void)n_in; (void)out_size;
    const float* q    = (const float*)d_in[0];
    const float* k    = (const float*)d_in[1];
    const float* v    = (const float*)d_in[2];
    const float* bias = (const float*)d_in[3];
    float* out = (float*)d_out;

    // Host-side attribute set; not a stream op, safe under graph capture,
    // idempotent and deterministic.
    cudaFuncSetAttribute(fa_tf32_pipe, cudaFuncAttributeMaxDynamicSharedMemorySize,
                         SMEM_BYTES);

    dim3 grid(Sc / BM, Hc, Bc);
    fa_tf32_pipe<<<grid, 256, SMEM_BYTES>>>(q, k, v, bias, out);
}

// round 5
// speedup vs baseline: 1.3217x; 1.3217x over previous
#include <cuda_runtime.h>
#include <cstdint>
#include <float.h>

// Problem constants
constexpr int Bc = 2, Hc = 16, Sc = 2048, Dc = 64;
constexpr int BM = 128, BN = 64;
constexpr int LDH = 72;                // smem pitch in halves (36 words): bank = 4g+t, conflict-free
constexpr float SCL = 0.18033688011f;  // 0.125 * log2(e)

// pack two fp32 -> f16x2 (lo = first arg). Convention verified against the
// bf16 macro in ptx_helpers: second PTX source lands in the LOW half.
__device__ __forceinline__ uint32_t pack_f16x2(float lo, float hi) {
    uint32_t r;
    asm("cvt.rn.f16x2.f32 %0, %1, %2;" : "=r"(r) : "f"(hi), "f"(lo));
    return r;
}

__device__ __forceinline__ float ex2(float x) {
    float y;
    asm("ex2.approx.ftz.f32 %0, %1;" : "=f"(y) : "f"(x));
    return y;
}

__device__ __forceinline__ void mma_f16(float c[4], const uint32_t a[4],
                                        uint32_t b0, uint32_t b1) {
    asm volatile(
        "mma.sync.aligned.m16n8k16.row.col.f32.f16.f16.f32 "
        "{%0,%1,%2,%3}, {%4,%5,%6,%7}, {%8,%9}, {%0,%1,%2,%3};"
        : "+f"(c[0]), "+f"(c[1]), "+f"(c[2]), "+f"(c[3])
        : "r"(a[0]), "r"(a[1]), "r"(a[2]), "r"(a[3]), "r"(b0), "r"(b1));
}

// Flash-attention, fp16 mma.sync m16n8k16 (fp32 accumulate), 2 CTAs/SM.
// Grid (S/128, H, B), 8 warps; warp w owns q-rows [w*16, w*16+16).
// K in smem row-major [j][d] halves; V stored TRANSPOSED [d][j] halves so both
// GEMMs read B fragments as single 32-bit words at identical conflict-free
// addressing. P stays in fp32 accumulators; packed straight into the A slots
// of GEMM2 (m16n8k16 layout makes this permutation-free).
__global__ __launch_bounds__(256, 2)
void fa_f16_kernel(const float* __restrict__ q, const float* __restrict__ k,
                   const float* __restrict__ v, const float* __restrict__ bias,
                   float* __restrict__ out)
{
    __shared__ __align__(16) uint16_t sKh[64 * LDH];  // K [j][d]
    __shared__ __align__(16) uint16_t sVt[64 * LDH];  // V transposed [d][j]

    const int qt = (int)gridDim.x - 1 - (int)blockIdx.x;  // heavy CTAs first
    const int h = blockIdx.y;
    const int b = blockIdx.z;

    const int tid = threadIdx.x;
    const int wid = tid >> 5;
    const int lane = tid & 31;
    const int g = lane >> 2;
    const int t = lane & 3;
    const int i0w = wid * 16;

    const size_t bh = (size_t)b * Hc + h;
    const float* qb    = q    + (bh * Sc + (size_t)qt * BM) * Dc;
    const float* kb    = k    + bh * Sc * Dc;
    const float* vb    = v    + bh * Sc * Dc;
    const float* biasb = bias + (bh * Sc + (size_t)qt * BM) * Sc;
    float* outb        = out  + (bh * Sc + (size_t)qt * BM) * Dc;

    // ---- Q fragments straight from global (once per CTA) ----
    // a0=(g,2t..2t+1) a1=(g+8,..) a2=(g,2t+8..) a3=(g+8,2t+8..), k-step = 16 d
    uint32_t qa[4][4];
    #pragma unroll
    for (int ks = 0; ks < 4; ks++) {
        const float* q0 = qb + (size_t)(i0w + g) * Dc + ks * 16 + 2 * t;
        const float* q1 = q0 + (size_t)8 * Dc;
        float2 f;
        f = *reinterpret_cast<const float2*>(q0);     qa[ks][0] = pack_f16x2(f.x, f.y);
        f = *reinterpret_cast<const float2*>(q1);     qa[ks][1] = pack_f16x2(f.x, f.y);
        f = *reinterpret_cast<const float2*>(q0 + 8); qa[ks][2] = pack_f16x2(f.x, f.y);
        f = *reinterpret_cast<const float2*>(q1 + 8); qa[ks][3] = pack_f16x2(f.x, f.y);
    }

    // Loader decompositions
    const int kj = tid >> 2, kq = tid & 3, kd0 = kq * 16;   // K: 1 row, 16 d each
    const int vjp = tid & 31, vd0 = (tid >> 5) * 8;         // V: 2 rows, 8 d each

    // Online-softmax state
    float m[2] = {-FLT_MAX, -FLT_MAX};
    float l[2] = {0.f, 0.f};
    float o[8][4];
    #pragma unroll
    for (int nf = 0; nf < 8; nf++)
        #pragma unroll
        for (int e = 0; e < 4; e++) o[nf][e] = 0.f;

    const int ntiles = 2 * qt + 2;

    for (int jt = 0; jt < ntiles; jt++) {
        const int jbase = jt * BN;

        __syncthreads();  // previous tile's readers done

        // ---- Load K tile: row kj, d[kd0..kd0+15] -> sKh (fp16) ----
        {
            const float* kr = kb + (size_t)(jbase + kj) * Dc + kd0;
            float4 f0 = *reinterpret_cast<const float4*>(kr);
            float4 f1 = *reinterpret_cast<const float4*>(kr + 4);
            float4 f2 = *reinterpret_cast<const float4*>(kr + 8);
            float4 f3 = *reinterpret_cast<const float4*>(kr + 12);
            uint4 w0, w1;
            w0.x = pack_f16x2(f0.x, f0.y); w0.y = pack_f16x2(f0.z, f0.w);
            w0.z = pack_f16x2(f1.x, f1.y); w0.w = pack_f16x2(f1.z, f1.w);
            w1.x = pack_f16x2(f2.x, f2.y); w1.y = pack_f16x2(f2.z, f2.w);
            w1.z = pack_f16x2(f3.x, f3.y); w1.w = pack_f16x2(f3.z, f3.w);
            uint4* dst = reinterpret_cast<uint4*>(&sKh[kj * LDH + kd0]);
            dst[0] = w0;
            dst[1] = w1;
        }
        // ---- Load V tile transposed: rows 2vjp,2vjp+1, d[vd0..vd0+7] -> sVt[d][j] ----
        {
            const float* v0p = vb + (size_t)(jbase + 2 * vjp) * Dc + vd0;
            const float* v1p = v0p + Dc;
            float4 a0 = *reinterpret_cast<const float4*>(v0p);
            float4 a1 = *reinterpret_cast<const float4*>(v0p + 4);
            float4 b0 = *reinterpret_cast<const float4*>(v1p);
            float4 b1 = *reinterpret_cast<const float4*>(v1p + 4);
            uint32_t* dv = reinterpret_cast<uint32_t*>(sVt);
            dv[(vd0 + 0) * (LDH / 2) + vjp] = pack_f16x2(a0.x, b0.x);
            dv[(vd0 + 1) * (LDH / 2) + vjp] = pack_f16x2(a0.y, b0.y);
            dv[(vd0 + 2) * (LDH / 2) + vjp] = pack_f16x2(a0.z, b0.z);
            dv[(vd0 + 3) * (LDH / 2) + vjp] = pack_f16x2(a0.w, b0.w);
            dv[(vd0 + 4) * (LDH / 2) + vjp] = pack_f16x2(a1.x, b1.x);
            dv[(vd0 + 5) * (LDH / 2) + vjp] = pack_f16x2(a1.y, b1.y);
            dv[(vd0 + 6) * (LDH / 2) + vjp] = pack_f16x2(a1.z, b1.z);
            dv[(vd0 + 7) * (LDH / 2) + vjp] = pack_f16x2(a1.w, b1.w);
        }

        const bool active = (qt * BM + i0w + 15) >= jbase;

        // ---- Bias prefetch *8 into accumulators (overlaps the barrier) ----
        float c[8][4];
        if (active) {
            const float* bp0 = biasb + (size_t)(i0w + g) * Sc + jbase + 2 * t;
            const float* bp1 = bp0 + (size_t)8 * Sc;
            #pragma unroll
            for (int nf = 0; nf < 8; nf++) {
                float2 x0 = *reinterpret_cast<const float2*>(bp0 + nf * 8);
                float2 x1 = *reinterpret_cast<const float2*>(bp1 + nf * 8);
                c[nf][0] = x0.x * 8.f;
                c[nf][1] = x0.y * 8.f;
                c[nf][2] = x1.x * 8.f;
                c[nf][3] = x1.y * 8.f;
            }
        }

        __syncthreads();  // tiles ready

        if (!active) continue;

        const uint32_t* sKw = reinterpret_cast<const uint32_t*>(sKh);
        const uint32_t* sVw = reinterpret_cast<const uint32_t*>(sVt);

        // ---- GEMM1: C += Q @ K^T.  b0 = K[8nf+g][16ks+2t..+1] (one word) ----
        #pragma unroll
        for (int ks = 0; ks < 4; ks++) {
            #pragma unroll
            for (int nf = 0; nf < 8; nf++) {
                const int base = (nf * 8 + g) * (LDH / 2) + ks * 8 + t;
                mma_f16(c[nf], qa[ks], sKw[base], sKw[base + 4]);
            }
        }

        // ---- scale (log2 domain; bias pre-folded), causal mask ----
        #pragma unroll
        for (int nf = 0; nf < 8; nf++)
            #pragma unroll
            for (int e = 0; e < 4; e++) c[nf][e] *= SCL;

        if (jt >= 2 * qt) {
            const int row0 = qt * BM + i0w + g;
            const int row1 = row0 + 8;
            #pragma unroll
            for (int nf = 0; nf < 8; nf++) {
                const int col = jbase + nf * 8 + 2 * t;
                if (col     > row0) c[nf][0] = -FLT_MAX;
                if (col + 1 > row0) c[nf][1] = -FLT_MAX;
                if (col     > row1) c[nf][2] = -FLT_MAX;
                if (col + 1 > row1) c[nf][3] = -FLT_MAX;
            }
        }

        // ---- Online softmax ----
        #pragma unroll
        for (int r = 0; r < 2; r++) {
            float rmax = -FLT_MAX;
            #pragma unroll
            for (int nf = 0; nf < 8; nf++)
                rmax = fmaxf(rmax, fmaxf(c[nf][2 * r], c[nf][2 * r + 1]));
            rmax = fmaxf(rmax, __shfl_xor_sync(0xffffffffu, rmax, 1));
            rmax = fmaxf(rmax, __shfl_xor_sync(0xffffffffu, rmax, 2));
            const float mnew = fmaxf(m[r], rmax);
            const float alpha = ex2(m[r] - mnew);
            float rsum = 0.f;
            #pragma unroll
            for (int nf = 0; nf < 8; nf++) {
                const float p0 = ex2(c[nf][2 * r]     - mnew);
                const float p1 = ex2(c[nf][2 * r + 1] - mnew);
                c[nf][2 * r] = p0;
                c[nf][2 * r + 1] = p1;
                rsum += p0 + p1;
            }
            rsum += __shfl_xor_sync(0xffffffffu, rsum, 1);
            rsum += __shfl_xor_sync(0xffffffffu, rsum, 2);
            l[r] = l[r] * alpha + rsum;
            m[r] = mnew;
            #pragma unroll
            for (int nf = 0; nf < 8; nf++) {
                o[nf][2 * r]     *= alpha;
                o[nf][2 * r + 1] *= alpha;
            }
        }

        // ---- GEMM2: O += P @ V.  A slots pack directly from c (k16 layout);
        //      b0 = Vt[8nf+g][16ks+2t..+1] (one word) ----
        #pragma unroll
        for (int ks = 0; ks < 4; ks++) {
            uint32_t pa[4];
            pa[0] = pack_f16x2(c[2 * ks][0],     c[2 * ks][1]);
            pa[1] = pack_f16x2(c[2 * ks][2],     c[2 * ks][3]);
            pa[2] = pack_f16x2(c[2 * ks + 1][0], c[2 * ks + 1][1]);
            pa[3] = pack_f16x2(c[2 * ks + 1][2], c[2 * ks + 1][3]);
            #pragma unroll
            for (int nf = 0; nf < 8; nf++) {
                const int base = (nf * 8 + g) * (LDH / 2) + ks * 8 + t;
                mma_f16(o[nf], pa, sVw[base], sVw[base + 4]);
            }
        }
    }

    // ---- Finalize ----
    #pragma unroll
    for (int r = 0; r < 2; r++) {
        const float inv = 1.f / l[r];
        const int row = i0w + g + 8 * r;
        #pragma unroll
        for (int nf = 0; nf < 8; nf++) {
            float2 res = make_float2(o[nf][2 * r] * inv, o[nf][2 * r + 1] * inv);
            *reinterpret_cast<float2*>(outb + (size_t)row * Dc + nf * 8 + 2 * t) = res;
        }
    }
}

extern "C" void kernel_launch(void* const* d_in, const int* in_sizes, int n_in,
                              void* d_out, int out_size)
{
    (void)in_sizes; (void)n_in; (void)out_size;
    const float* q    = (const float*)d_in[0];
    const float* k    = (const float*)d_in[1];
    const float* v    = (const float*)d_in[2];
    const float* bias = (const float*)d_in[3];
    float* out = (float*)d_out;

    dim3 grid(Sc / BM, Hc, Bc);
    fa_f16_kernel<<<grid, 256>>>(q, k, v, bias, out);
}

// round 6
// speedup vs baseline: 1.3327x; 1.0083x over previous
#include <cuda_runtime.h>
#include <cstdint>
#include <float.h>

// Problem constants
constexpr int Bc = 2, Hc = 16, Sc = 2048, Dc = 64;
constexpr int BM = 128, BN = 64;
constexpr int LDH = 72;                // smem pitch in halves (36 words): bank = 4g+t, conflict-free
constexpr float SCL = 0.18033688011f;  // 0.125 * log2(e)

// pack two fp32 -> f16x2 (lo = first arg). Convention verified against the
// bf16 macro in ptx_helpers: second PTX source lands in the LOW half.
__device__ __forceinline__ uint32_t pack_f16x2(float lo, float hi) {
    uint32_t r;
    asm("cvt.rn.f16x2.f32 %0, %1, %2;" : "=r"(r) : "f"(hi), "f"(lo));
    return r;
}

__device__ __forceinline__ float ex2(float x) {
    float y;
    asm("ex2.approx.ftz.f32 %0, %1;" : "=f"(y) : "f"(x));
    return y;
}

__device__ __forceinline__ void mma_f16(float c[4], const uint32_t a[4],
                                        uint32_t b0, uint32_t b1) {
    asm volatile(
        "mma.sync.aligned.m16n8k16.row.col.f32.f16.f16.f32 "
        "{%0,%1,%2,%3}, {%4,%5,%6,%7}, {%8,%9}, {%0,%1,%2,%3};"
        : "+f"(c[0]), "+f"(c[1]), "+f"(c[2]), "+f"(c[3])
        : "r"(a[0]), "r"(a[1]), "r"(a[2]), "r"(a[3]), "r"(b0), "r"(b1));
}

// Flash-attention, fp16 mma.sync m16n8k16 (fp32 accumulate), 2 CTAs/SM.
// Grid (S/128, H, B), 8 warps; warp w owns q-rows [w*16, w*16+16).
// K in smem row-major [j][d] halves; V stored TRANSPOSED [d][j] halves so both
// GEMMs read B fragments as single 32-bit words at identical conflict-free
// addressing. P stays in fp32 accumulators; packed straight into the A slots
// of GEMM2 (m16n8k16 layout makes this permutation-free).
__global__ __launch_bounds__(256, 2)
void fa_f16_kernel(const float* __restrict__ q, const float* __restrict__ k,
                   const float* __restrict__ v, const float* __restrict__ bias,
                   float* __restrict__ out)
{
    __shared__ __align__(16) uint16_t sKh[64 * LDH];  // K [j][d]
    __shared__ __align__(16) uint16_t sVt[64 * LDH];  // V transposed [d][j]

    const int qt = (int)gridDim.x - 1 - (int)blockIdx.x;  // heavy CTAs first
    const int h = blockIdx.y;
    const int b = blockIdx.z;

    const int tid = threadIdx.x;
    const int wid = tid >> 5;
    const int lane = tid & 31;
    const int g = lane >> 2;
    const int t = lane & 3;
    const int i0w = wid * 16;

    const size_t bh = (size_t)b * Hc + h;
    const float* qb    = q    + (bh * Sc + (size_t)qt * BM) * Dc;
    const float* kb    = k    + bh * Sc * Dc;
    const float* vb    = v    + bh * Sc * Dc;
    const float* biasb = bias + (bh * Sc + (size_t)qt * BM) * Sc;
    float* outb        = out  + (bh * Sc + (size_t)qt * BM) * Dc;

    // ---- Q fragments straight from global (once per CTA) ----
    // a0=(g,2t..2t+1) a1=(g+8,..) a2=(g,2t+8..) a3=(g+8,2t+8..), k-step = 16 d
    uint32_t qa[4][4];
    #pragma unroll
    for (int ks = 0; ks < 4; ks++) {
        const float* q0 = qb + (size_t)(i0w + g) * Dc + ks * 16 + 2 * t;
        const float* q1 = q0 + (size_t)8 * Dc;
        float2 f;
        f = *reinterpret_cast<const float2*>(q0);     qa[ks][0] = pack_f16x2(f.x, f.y);
        f = *reinterpret_cast<const float2*>(q1);     qa[ks][1] = pack_f16x2(f.x, f.y);
        f = *reinterpret_cast<const float2*>(q0 + 8); qa[ks][2] = pack_f16x2(f.x, f.y);
        f = *reinterpret_cast<const float2*>(q1 + 8); qa[ks][3] = pack_f16x2(f.x, f.y);
    }

    // Loader decompositions
    const int kj = tid >> 2, kq = tid & 3, kd0 = kq * 16;   // K: 1 row, 16 d each
    const int vjp = tid & 31, vd0 = (tid >> 5) * 8;         // V: 2 rows, 8 d each

    // Online-softmax state
    float m[2] = {-FLT_MAX, -FLT_MAX};
    float l[2] = {0.f, 0.f};
    float o[8][4];
    #pragma unroll
    for (int nf = 0; nf < 8; nf++)
        #pragma unroll
        for (int e = 0; e < 4; e++) o[nf][e] = 0.f;

    const int ntiles = 2 * qt + 2;

    for (int jt = 0; jt < ntiles; jt++) {
        const int jbase = jt * BN;

        __syncthreads();  // previous tile's readers done

        // ---- Load K tile: row kj, d[kd0..kd0+15] -> sKh (fp16) ----
        {
            const float* kr = kb + (size_t)(jbase + kj) * Dc + kd0;
            float4 f0 = *reinterpret_cast<const float4*>(kr);
            float4 f1 = *reinterpret_cast<const float4*>(kr + 4);
            float4 f2 = *reinterpret_cast<const float4*>(kr + 8);
            float4 f3 = *reinterpret_cast<const float4*>(kr + 12);
            uint4 w0, w1;
            w0.x = pack_f16x2(f0.x, f0.y); w0.y = pack_f16x2(f0.z, f0.w);
            w0.z = pack_f16x2(f1.x, f1.y); w0.w = pack_f16x2(f1.z, f1.w);
            w1.x = pack_f16x2(f2.x, f2.y); w1.y = pack_f16x2(f2.z, f2.w);
            w1.z = pack_f16x2(f3.x, f3.y); w1.w = pack_f16x2(f3.z, f3.w);
            uint4* dst = reinterpret_cast<uint4*>(&sKh[kj * LDH + kd0]);
            dst[0] = w0;
            dst[1] = w1;
        }
        // ---- Load V tile transposed: rows 2vjp,2vjp+1, d[vd0..vd0+7] -> sVt[d][j] ----
        {
            const float* v0p = vb + (size_t)(jbase + 2 * vjp) * Dc + vd0;
            const float* v1p = v0p + Dc;
            float4 a0 = *reinterpret_cast<const float4*>(v0p);
            float4 a1 = *reinterpret_cast<const float4*>(v0p + 4);
            float4 b0 = *reinterpret_cast<const float4*>(v1p);
            float4 b1 = *reinterpret_cast<const float4*>(v1p + 4);
            uint32_t* dv = reinterpret_cast<uint32_t*>(sVt);
            dv[(vd0 + 0) * (LDH / 2) + vjp] = pack_f16x2(a0.x, b0.x);
            dv[(vd0 + 1) * (LDH / 2) + vjp] = pack_f16x2(a0.y, b0.y);
            dv[(vd0 + 2) * (LDH / 2) + vjp] = pack_f16x2(a0.z, b0.z);
            dv[(vd0 + 3) * (LDH / 2) + vjp] = pack_f16x2(a0.w, b0.w);
            dv[(vd0 + 4) * (LDH / 2) + vjp] = pack_f16x2(a1.x, b1.x);
            dv[(vd0 + 5) * (LDH / 2) + vjp] = pack_f16x2(a1.y, b1.y);
            dv[(vd0 + 6) * (LDH / 2) + vjp] = pack_f16x2(a1.z, b1.z);
            dv[(vd0 + 7) * (LDH / 2) + vjp] = pack_f16x2(a1.w, b1.w);
        }

        const bool active = (qt * BM + i0w + 15) >= jbase;

        // ---- Bias prefetch *8 into accumulators (overlaps the barrier) ----
        float c[8][4];
        if (active) {
            const float* bp0 = biasb + (size_t)(i0w + g) * Sc + jbase + 2 * t;
            const float* bp1 = bp0 + (size_t)8 * Sc;
            #pragma unroll
            for (int nf = 0; nf < 8; nf++) {
                float2 x0 = *reinterpret_cast<const float2*>(bp0 + nf * 8);
                float2 x1 = *reinterpret_cast<const float2*>(bp1 + nf * 8);
                c[nf][0] = x0.x * 8.f;
                c[nf][1] = x0.y * 8.f;
                c[nf][2] = x1.x * 8.f;
                c[nf][3] = x1.y * 8.f;
            }
        }

        __syncthreads();  // tiles ready

        if (!active) continue;

        const uint32_t* sKw = reinterpret_cast<const uint32_t*>(sKh);
        const uint32_t* sVw = reinterpret_cast<const uint32_t*>(sVt);

        // ---- GEMM1: C += Q @ K^T.  b0 = K[8nf+g][16ks+2t..+1] (one word) ----
        #pragma unroll
        for (int ks = 0; ks < 4; ks++) {
            #pragma unroll
            for (int nf = 0; nf < 8; nf++) {
                const int base = (nf * 8 + g) * (LDH / 2) + ks * 8 + t;
                mma_f16(c[nf], qa[ks], sKw[base], sKw[base + 4]);
            }
        }

        // ---- scale (log2 domain; bias pre-folded), causal mask ----
        #pragma unroll
        for (int nf = 0; nf < 8; nf++)
            #pragma unroll
            for (int e = 0; e < 4; e++) c[nf][e] *= SCL;

        if (jt >= 2 * qt) {
            const int row0 = qt * BM + i0w + g;
            const int row1 = row0 + 8;
            #pragma unroll
            for (int nf = 0; nf < 8; nf++) {
                const int col = jbase + nf * 8 + 2 * t;
                if (col     > row0) c[nf][0] = -FLT_MAX;
                if (col + 1 > row0) c[nf][1] = -FLT_MAX;
                if (col     > row1) c[nf][2] = -FLT_MAX;
                if (col + 1 > row1) c[nf][3] = -FLT_MAX;
            }
        }

        // ---- Online softmax ----
        #pragma unroll
        for (int r = 0; r < 2; r++) {
            float rmax = -FLT_MAX;
            #pragma unroll
            for (int nf = 0; nf < 8; nf++)
                rmax = fmaxf(rmax, fmaxf(c[nf][2 * r], c[nf][2 * r + 1]));
            rmax = fmaxf(rmax, __shfl_xor_sync(0xffffffffu, rmax, 1));
            rmax = fmaxf(rmax, __shfl_xor_sync(0xffffffffu, rmax, 2));
            const float mnew = fmaxf(m[r], rmax);
            const float alpha = ex2(m[r] - mnew);
            float rsum = 0.f;
            #pragma unroll
            for (int nf = 0; nf < 8; nf++) {
                const float p0 = ex2(c[nf][2 * r]     - mnew);
                const float p1 = ex2(c[nf][2 * r + 1] - mnew);
                c[nf][2 * r] = p0;
                c[nf][2 * r + 1] = p1;
                rsum += p0 + p1;
            }
            rsum += __shfl_xor_sync(0xffffffffu, rsum, 1);
            rsum += __shfl_xor_sync(0xffffffffu, rsum, 2);
            l[r] = l[r] * alpha + rsum;
            m[r] = mnew;
            #pragma unroll
            for (int nf = 0; nf < 8; nf++) {
                o[nf][2 * r]     *= alpha;
                o[nf][2 * r + 1] *= alpha;
            }
        }

        // ---- GEMM2: O += P @ V.  A slots pack directly from c (k16 layout);
        //      b0 = Vt[8nf+g][16ks+2t..+1] (one word) ----
        #pragma unroll
        for (int ks = 0; ks < 4; ks++) {
            uint32_t pa[4];
            pa[0] = pack_f16x2(c[2 * ks][0],     c[2 * ks][1]);
            pa[1] = pack_f16x2(c[2 * ks][2],     c[2 * ks][3]);
            pa[2] = pack_f16x2(c[2 * ks + 1][0], c[2 * ks + 1][1]);
            pa[3] = pack_f16x2(c[2 * ks + 1][2], c[2 * ks + 1][3]);
            #pragma unroll
            for (int nf = 0; nf < 8; nf++) {
                const int base = (nf * 8 + g) * (LDH / 2) + ks * 8 + t;
                mma_f16(o[nf], pa, sVw[base], sVw[base + 4]);
            }
        }
    }

    // ---- Finalize ----
    #pragma unroll
    for (int r = 0; r < 2; r++) {
        const float inv = 1.f / l[r];
        const int row = i0w + g + 8 * r;
        #pragma unroll
        for (int nf = 0; nf < 8; nf++) {
            float2 res = make_float2(o[nf][2 * r] * inv, o[nf][2 * r + 1] * inv);
            *reinterpret_cast<float2*>(outb + (size_t)row * Dc + nf * 8 + 2 * t) = res;
        }
    }
}

extern "C" void kernel_launch(void* const* d_in, const int* in_sizes, int n_in,
                              void* d_out, int out_size)
{
    (void)in_sizes; (void)n_in; (void)out_size;
    const float* q    = (const float*)d_in[0];
    const float* k    = (const float*)d_in[1];
    const float* v    = (const float*)d_in[2];
    const float* bias = (const float*)d_in[3];
    float* out = (float*)d_out;

    dim3 grid(Sc / BM, Hc, Bc);
    fa_f16_kernel<<<grid, 256>>>(q, k, v, bias, out);
}